// round 9
// baseline (speedup 1.0000x reference)
#include <cuda_runtime.h>
#include <math.h>
#include <stdint.h>

#define NG 512
#define IMG_H 256
#define IMG_W 256
#define TW 8
#define TH 8
#define NTHR 64

#define FXC 256.0f
#define FYC 256.0f
#define LIMX (1.3f * 0.5f)
#define LIMY (1.3f * 0.5f)

// Per-gaussian preprocessed data (unsorted, indexed by gaussian id):
//  gA: px, py, ca, cb        gB: cc, op, cr, cg
//  gC: cb(blue), invdepth, depth, r2
//  gCull: px, py, r2 (cull radius^2; <0 => never visible), depth
__device__ float4 gA[NG];
__device__ float4 gB[NG];
__device__ float4 gC[NG];
__device__ float4 gCull[NG];

// ---------------------------------------------------------------------------
// Preprocess: one thread per gaussian. All MUFU-heavy math happens exactly
// once per gaussian.
// ---------------------------------------------------------------------------
__global__ void __launch_bounds__(64)
preprocess_kernel(const float* __restrict__ means3D,
                  const float* __restrict__ opac,
                  const float* __restrict__ colors,
                  const float* __restrict__ scales,
                  const float* __restrict__ rots,
                  const float* __restrict__ view,
                  const float* __restrict__ proj,
                  float* __restrict__ radii_out)
{
    const int j = blockIdx.x * 64 + threadIdx.x;
    if (j >= NG) return;

    const float V00 = view[0], V01 = view[1], V02 = view[2],  V03 = view[3];
    const float V10 = view[4], V11 = view[5], V12 = view[6],  V13 = view[7];
    const float V20 = view[8], V21 = view[9], V22 = view[10], V23 = view[11];

    const float m0 = means3D[3 * j + 0];
    const float m1 = means3D[3 * j + 1];
    const float m2 = means3D[3 * j + 2];

    const float t0 = V00 * m0 + V01 * m1 + V02 * m2 + V03;
    const float t1 = V10 * m0 + V11 * m1 + V12 * m2 + V13;
    const float depth = V20 * m0 + V21 * m1 + V22 * m2 + V23;

    const float c0 = proj[0]  * m0 + proj[1]  * m1 + proj[2]  * m2 + proj[3];
    const float c1 = proj[4]  * m0 + proj[5]  * m1 + proj[6]  * m2 + proj[7];
    const float c3 = proj[12] * m0 + proj[13] * m1 + proj[14] * m2 + proj[15];
    const float pw = __fdividef(1.0f, c3 + 1e-7f);
    const float px = ((c0 * pw + 1.0f) * (float)IMG_W - 1.0f) * 0.5f;
    const float py = ((c1 * pw + 1.0f) * (float)IMG_H - 1.0f) * 0.5f;

    const float4 q = reinterpret_cast<const float4*>(rots)[j];
    float qw = q.x, qx = q.y, qy = q.z, qz = q.w;
    const float qn = rsqrtf(qw * qw + qx * qx + qy * qy + qz * qz);
    qw *= qn; qx *= qn; qy *= qn; qz *= qn;
    const float R00 = 1.0f - 2.0f * (qy * qy + qz * qz);
    const float R01 = 2.0f * (qx * qy - qw * qz);
    const float R02 = 2.0f * (qx * qz + qw * qy);
    const float R10 = 2.0f * (qx * qy + qw * qz);
    const float R11 = 1.0f - 2.0f * (qx * qx + qz * qz);
    const float R12 = 2.0f * (qy * qz - qw * qx);
    const float R20 = 2.0f * (qx * qz - qw * qy);
    const float R21 = 2.0f * (qy * qz + qw * qx);
    const float R22 = 1.0f - 2.0f * (qx * qx + qy * qy);

    const float s0 = scales[3 * j + 0];
    const float s1 = scales[3 * j + 1];
    const float s2 = scales[3 * j + 2];

    const float M00 = R00 * s0, M01 = R01 * s1, M02 = R02 * s2;
    const float M10 = R10 * s0, M11 = R11 * s1, M12 = R12 * s2;
    const float M20 = R20 * s0, M21 = R21 * s1, M22 = R22 * s2;
    const float C00 = M00 * M00 + M01 * M01 + M02 * M02;
    const float C01 = M00 * M10 + M01 * M11 + M02 * M12;
    const float C02 = M00 * M20 + M01 * M21 + M02 * M22;
    const float C11 = M10 * M10 + M11 * M11 + M12 * M12;
    const float C12 = M10 * M20 + M11 * M21 + M12 * M22;
    const float C22 = M20 * M20 + M21 * M21 + M22 * M22;

    const float invz = __fdividef(1.0f, depth);
    const float ttx = fminf(fmaxf(t0 * invz, -LIMX), LIMX) * depth;
    const float tty = fminf(fmaxf(t1 * invz, -LIMY), LIMY) * depth;
    const float J00 = FXC * invz;
    const float J02 = -FXC * ttx * invz * invz;
    const float J11 = FYC * invz;
    const float J12 = -FYC * tty * invz * invz;

    const float T00 = J00 * V00 + J02 * V20;
    const float T01 = J00 * V01 + J02 * V21;
    const float T02 = J00 * V02 + J02 * V22;
    const float T10 = J11 * V10 + J12 * V20;
    const float T11 = J11 * V11 + J12 * V21;
    const float T12 = J11 * V12 + J12 * V22;

    const float u0 = C00 * T00 + C01 * T01 + C02 * T02;
    const float u1 = C01 * T00 + C11 * T01 + C12 * T02;
    const float u2 = C02 * T00 + C12 * T01 + C22 * T02;
    const float w0 = C00 * T10 + C01 * T11 + C02 * T12;
    const float w1 = C01 * T10 + C11 * T11 + C12 * T12;
    const float w2 = C02 * T10 + C12 * T11 + C22 * T12;
    const float a = T00 * u0 + T01 * u1 + T02 * u2 + 0.3f;
    const float b = T10 * u0 + T11 * u1 + T12 * u2;
    const float c = T10 * w0 + T11 * w1 + T12 * w2 + 0.3f;

    const float det = a * c - b * b;
    const float inv_det = __fdividef(1.0f, (det != 0.0f) ? det : 1.0f);
    const float ca =  c * inv_det;
    const float cb = -b * inv_det;
    const float cc =  a * inv_det;

    const float mid = 0.5f * (a + c);
    const float lam = mid + sqrtf(fmaxf(mid * mid - det, 0.1f));

    radii_out[j] = (float)((int)ceilf(3.0f * sqrtf(lam)));

    const bool valid = (depth > 0.2f) && (det > 0.0f);
    const float op = opac[j];

    // Exact cull radius^2: alpha < 1/255 guaranteed beyond it.
    float r2 = -1.0f;
    if (valid && op * 255.0f > 1.0f) {
        r2 = 2.0f * lam * __logf(255.0f * op) + 1e-2f;
        if (r2 < 0.0f) r2 = -1.0f;
    }

    gA[j] = make_float4(px, py, ca, cb);
    gB[j] = make_float4(cc, op, colors[3 * j + 0], colors[3 * j + 1]);
    gC[j] = make_float4(colors[3 * j + 2],
                        __fdividef(1.0f, fmaxf(depth, 1e-6f)),
                        depth, r2);
    gCull[j] = make_float4(px, py, r2, depth);
}

// ---------------------------------------------------------------------------
// Raster: each block = one 8x8 tile (1024 blocks, ~7 CTAs/SM for latency
// hiding). Cull all 512 gaussians (1 LDG each, deep MLP), ballot-compact
// survivors (id order), rank-sort by (depth, id) — the reference's stable
// depth argsort among contributors — then composite front-to-back.
// ---------------------------------------------------------------------------
__global__ void __launch_bounds__(NTHR)
raster_kernel(const float* __restrict__ bg,
              const float* __restrict__ mask,
              float* __restrict__ out)
{
    __shared__ float4 ssA[NG];
    __shared__ float4 ssB[NG];
    __shared__ float4 ssC[NG];
    __shared__ int    ord[NG];
    __shared__ uint32_t bm[NG / 32];
    __shared__ int wpre[NG / 32 + 1];

    const int tid  = threadIdx.y * TW + threadIdx.x;
    const int warp = tid >> 5;           // 0..1
    const int lane = tid & 31;

    const float tx0 = (float)(blockIdx.x * TW);
    const float tx1 = tx0 + (float)(TW - 1);
    const float ty0 = (float)(blockIdx.y * TH);
    const float ty1 = ty0 + (float)(TH - 1);

    // Phase 1: cull. j = k*64 + warp*32 + lane -> word index k*2 + warp.
    #pragma unroll
    for (int k = 0; k < NG / NTHR; ++k) {
        const int j = k * NTHR + tid;
        const float4 cg = gCull[j];
        const float cx = fminf(fmaxf(cg.x, tx0), tx1);
        const float cy = fminf(fmaxf(cg.y, ty0), ty1);
        const float ddx = cg.x - cx;
        const float ddy = cg.y - cy;
        const uint32_t bal = __ballot_sync(0xFFFFFFFFu,
                                           ddx * ddx + ddy * ddy <= cg.z);
        if (lane == 0) bm[k * 2 + warp] = bal;
    }
    __syncthreads();

    if (tid == 0) {
        int acc = 0;
        #pragma unroll
        for (int k = 0; k < NG / 32; ++k) { wpre[k] = acc; acc += __popc(bm[k]); }
        wpre[NG / 32] = acc;
    }
    __syncthreads();

    // Phase 2: compaction (preserves gaussian-id order); survivor data is
    // loaded from global only here (~15 gaussians per tile).
    #pragma unroll
    for (int k = 0; k < NG / NTHR; ++k) {
        const int j = k * NTHR + tid;
        const uint32_t w = bm[j >> 5];
        const uint32_t bit = 1u << (j & 31);
        if (w & bit) {
            const int pos = wpre[j >> 5] + __popc(w & (bit - 1u));
            ssA[pos] = gA[j];
            ssB[pos] = gB[j];
            ssC[pos] = gC[j];
        }
    }
    __syncthreads();
    const int cnt = wpre[NG / 32];

    // Phase 3: rank-sort survivors by (depth, id). Slots are in id order, so
    // the id tie-break is the slot index. Unique keys => deterministic.
    for (int e = tid; e < cnt; e += NTHR) {
        const float de = ssC[e].z;
        int rank = 0;
        for (int m = 0; m < cnt; ++m) {
            const float dm = ssC[m].z;
            rank += (dm < de) || ((dm == de) && (m < e));
        }
        ord[rank] = e;
    }
    __syncthreads();

    // Phase 4: front-to-back composite (one pixel per thread)
    const int x = blockIdx.x * TW + threadIdx.x;
    const int y = blockIdx.y * TH + threadIdx.y;
    const float fx = (float)x;
    const float fy = (float)y;

    float T = 1.0f, aR = 0.0f, aG = 0.0f, aB = 0.0f, aD = 0.0f;

    for (int n = 0; n < cnt; ++n) {
        const int pos = ord[n];
        const float4 A = ssA[pos];
        const float dx = fx - A.x;
        const float dy = fy - A.y;
        const float4 B = ssB[pos];
        const float power = -0.5f * (A.z * dx * dx) - A.w * dx * dy
                            - 0.5f * (B.x * dy * dy);
        if (power > 0.0f) continue;
        const float alpha = fminf(0.99f, B.y * __expf(power));
        if (alpha < (1.0f / 255.0f)) continue;
        const float4 C = ssC[pos];
        const float w = alpha * T;
        aR += w * B.z;
        aG += w * B.w;
        aB += w * C.x;
        aD += w * C.y;
        T *= (1.0f - alpha);
        if (T < 1e-7f) break;
    }

    const int pix = y * IMG_W + x;
    const float m = mask[pix];
    const int HW = IMG_H * IMG_W;
    out[0 * HW + pix] = (aR + T * bg[0]) * m;
    out[1 * HW + pix] = (aG + T * bg[1]) * m;
    out[2 * HW + pix] = (aB + T * bg[2]) * m;
    out[3 * HW + NG + pix] = aD * m;   // invd after color(3*HW) + radii(NG)
}

// ---------------------------------------------------------------------------
extern "C" void kernel_launch(void* const* d_in, const int* in_sizes, int n_in,
                              void* d_out, int out_size)
{
    const float* means3D = (const float*)d_in[0];
    // d_in[1] = means2D (unused by reference math)
    const float* opac    = (const float*)d_in[2];
    const float* colors  = (const float*)d_in[3];
    const float* scales  = (const float*)d_in[4];
    const float* rots    = (const float*)d_in[5];
    const float* view    = (const float*)d_in[6];
    const float* proj    = (const float*)d_in[7];
    const float* bg      = (const float*)d_in[8];
    const float* mask    = (const float*)d_in[9];
    float* out = (float*)d_out;

    float* radii_out = out + 3 * IMG_H * IMG_W;

    preprocess_kernel<<<8, 64>>>(means3D, opac, colors, scales, rots,
                                 view, proj, radii_out);

    dim3 blk(TW, TH);
    dim3 grd(IMG_W / TW, IMG_H / TH);
    raster_kernel<<<grd, blk>>>(bg, mask, out);
}